// round 1
// baseline (speedup 1.0000x reference)
#include <cuda_runtime.h>
#include <math.h>

#define B_IMGS   64
#define NBLK     4096
#define NLIN     16384
#define NCHR     16384
#define TOPK     100
#define KSEL     128      // select top-128 by logit, re-rank by exact sigmoid
#define NTHREADS 512
#define MAXLOC   32       // 16384 / 512
#define CANDCAP  512

// Output layout (float32), reference return order (*blk, *lin, *chr):
//  blk_data [64,100,4]  @ 0
//  blk_scores [64,100]  @ 25600
//  blk_keep  [64,100]   @ 32000
//  lin_data [64,100,4]  @ 38400
//  lin_scores [64,100]  @ 64000
//  lin_keep  [64,100]   @ 70400
//  chr_data [64,100,16] @ 76800
//  chr_scores [64,100]  @ 179200
//  chr_keep  [64,100]   @ 185600   (total 192000)

struct SharedState {
    int totals[32];
    int cnt;
    int flag_any_vk;
    int argmax_idx;
    int pad;
    unsigned int ckey[CANDCAP];
    int          cidx[CANDCAP];
    float        cprob[CANDCAP];
    float sval[TOPK];
    int   sidx[TOPK];
    float sbox[TOPK][4];
    float sarea[TOPK];
    float sbelong[TOPK];
    int   skeep[TOPK];
    float sdat[TOPK][16];
};

__global__ void __launch_bounds__(NTHREADS)
postprocess_kernel(const float* __restrict__ blk_logit,
                   const float* __restrict__ lin_logit,
                   const float* __restrict__ chr_logit,
                   const float* __restrict__ blk_raw,
                   const float* __restrict__ lin_raw,
                   const float* __restrict__ chr_raw,
                   const float* __restrict__ tsz,
                   float* __restrict__ out)
{
    __shared__ SharedState sm;
    const int b     = blockIdx.x;
    const int level = blockIdx.y;
    const int tid   = threadIdx.x;

    const int N = (level == 0) ? NBLK : NLIN;
    const float* logit = (level == 0) ? blk_logit : (level == 1) ? lin_logit : chr_logit;
    const float* lb = logit + (size_t)b * N;

    // ---- load logits -> monotone uint keys, kept in registers ----
    unsigned int lk[MAXLOC];
#pragma unroll
    for (int r = 0; r < MAXLOC; ++r) {
        int i = tid + r * NTHREADS;
        unsigned int key = 0u;   // pad = smallest possible key (excluded: pivot >= 1)
        if (i < N) {
            unsigned int u = __float_as_uint(lb[i]);
            key = u ^ ((u >> 31) ? 0xFFFFFFFFu : 0x80000000u);
        }
        lk[r] = key;
    }

    if (tid < 32) sm.totals[tid] = 0;
    if (tid == 0) { sm.cnt = 0; sm.flag_any_vk = 0; sm.argmax_idx = 0; }
    __syncthreads();

    // ---- bitwise binary search for the KSEL-th largest key ----
    unsigned int prefix = 0u;
    for (int bit = 31; bit >= 0; --bit) {
        unsigned int cand = prefix | (1u << bit);
        int c = 0;
#pragma unroll
        for (int r = 0; r < MAXLOC; ++r) c += (lk[r] >= cand) ? 1 : 0;
#pragma unroll
        for (int off = 16; off > 0; off >>= 1) c += __shfl_down_sync(0xFFFFFFFFu, c, off);
        if ((tid & 31) == 0 && c) atomicAdd(&sm.totals[bit], c);
        __syncthreads();
        if (sm.totals[bit] >= KSEL) prefix = cand;
    }
    // prefix = largest P with count(key >= P) >= KSEL  (exact pivot)

    // ---- gather all candidates with key >= pivot ----
#pragma unroll
    for (int r = 0; r < MAXLOC; ++r) {
        int i = tid + r * NTHREADS;
        if (i < N && lk[r] >= prefix) {
            int pos = atomicAdd(&sm.cnt, 1);
            if (pos < CANDCAP) { sm.ckey[pos] = lk[r]; sm.cidx[pos] = i; }
        }
    }
    __syncthreads();
    const int M = min(sm.cnt, CANDCAP);

    // ---- exact (correctly-rounded) f32 sigmoid per candidate ----
    if (tid < M) {
        unsigned int key = sm.ckey[tid];
        unsigned int u = key ^ ((key & 0x80000000u) ? 0x80000000u : 0xFFFFFFFFu);
        float x = __uint_as_float(u);
        double e = exp(-(double)x);
        sm.cprob[tid] = (float)(1.0 / (1.0 + e));
    }
    __syncthreads();

    // ---- rank candidates by (prob desc, index asc) — lax.top_k semantics ----
    if (tid < M) {
        float pm = sm.cprob[tid];
        int   im = sm.cidx[tid];
        int rank = 0;
        for (int j = 0; j < M; ++j) {
            float pj = sm.cprob[j];
            int   ij = sm.cidx[j];
            rank += (pj > pm || (pj == pm && ij < im)) ? 1 : 0;
        }
        if (rank < TOPK) { sm.sval[rank] = pm; sm.sidx[rank] = im; }
    }
    __syncthreads();

    const float hh = tsz[2 * b + 0];   // img_h = tsize[0]
    const float ww = tsz[2 * b + 1];   // img_w = tsize[1]

    // ---- per-detection geometry ----
    if (tid < TOPK) {
        const int k  = tid;
        const int si = sm.sidx[k];
        float x1, y1, x2, y2;

        if (level == 2) {
            // bezier: scale_pts = tile([h,w], 8) -> even coords * h, odd * w
            const float* rp = chr_raw + ((size_t)b * NCHR + (size_t)si) * 16;
            float ctrl[16];
#pragma unroll
            for (int j = 0; j < 8; ++j) {
                ctrl[2 * j]     = rp[2 * j]     * hh;
                ctrl[2 * j + 1] = rp[2 * j + 1] * ww;
            }
            float mnx = 1e30f, mny = 1e30f, mxx = -1e30f, mxy = -1e30f;
#pragma unroll
            for (int s = 0; s < 10; ++s) {
                float t  = (float)s * (1.0f / 9.0f);
                float ti = 1.0f - t;
                float b0 = ti * ti * ti;
                float b1 = 3.0f * t * ti * ti;
                float b2 = 3.0f * t * t * ti;
                float b3 = t * t * t;
                float xt = b0 * ctrl[0] + b1 * ctrl[2]  + b2 * ctrl[4]  + b3 * ctrl[6];
                float yt = b0 * ctrl[1] + b1 * ctrl[3]  + b2 * ctrl[5]  + b3 * ctrl[7];
                float xb = b0 * ctrl[8] + b1 * ctrl[10] + b2 * ctrl[12] + b3 * ctrl[14];
                float yb = b0 * ctrl[9] + b1 * ctrl[11] + b2 * ctrl[13] + b3 * ctrl[15];
                mnx = fminf(mnx, fminf(xt, xb));
                mny = fminf(mny, fminf(yt, yb));
                mxx = fmaxf(mxx, fmaxf(xt, xb));
                mxy = fmaxf(mxy, fmaxf(yt, yb));
            }
            x1 = mnx; y1 = mny; x2 = mxx; y2 = mxy;
#pragma unroll
            for (int j = 0; j < 16; ++j) sm.sdat[k][j] = ctrl[j];
        } else {
            const float* rp = (level == 0)
                ? blk_raw + ((size_t)b * NBLK + (size_t)si) * 4
                : lin_raw + ((size_t)b * NLIN + (size_t)si) * 4;
            float cx = rp[0], cy = rp[1], bw = rp[2], bh = rp[3];
            x1 = (cx - 0.5f * bw) * ww;
            y1 = (cy - 0.5f * bh) * hh;
            x2 = (cx + 0.5f * bw) * ww;
            y2 = (cy + 0.5f * bh) * hh;
            if (level == 0) {   // blocks: clip to [0, (w,h,w,h)]
                x1 = fminf(fmaxf(x1, 0.0f), ww);
                y1 = fminf(fmaxf(y1, 0.0f), hh);
                x2 = fminf(fmaxf(x2, 0.0f), ww);
                y2 = fminf(fmaxf(y2, 0.0f), hh);
            }
            sm.sdat[k][0] = x1; sm.sdat[k][1] = y1;
            sm.sdat[k][2] = x2; sm.sdat[k][3] = y2;
        }

        sm.sbox[k][0] = x1; sm.sbox[k][1] = y1;
        sm.sbox[k][2] = x2; sm.sbox[k][3] = y2;
        sm.sarea[k] = (x2 - x1) * (y2 - y1);

        bool kp   = sm.sval[k] > 0.1f;
        bool anyk = sm.sval[0] > 0.1f;   // vals sorted desc => any() == vals[0] > thr
        if (!anyk) kp = (k == 0);
        sm.skeep[k] = kp ? 1 : 0;

        if (level > 0) {
            const float* pr = (level == 1)
                ? blk_raw + ((size_t)b * NBLK + (size_t)(si >> 2)) * 4   // ef=4
                : lin_raw + ((size_t)b * NLIN + (size_t)si) * 4;         // ef=1
            float pcx = pr[0], pcy = pr[1], pw = pr[2], ph = pr[3];
            float px1 = (pcx - 0.5f * pw) * ww;
            float py1 = (pcy - 0.5f * ph) * hh;
            float px2 = (pcx + 0.5f * pw) * ww;
            float py2 = (pcy + 0.5f * ph) * hh;
            float ix1 = fmaxf(x1, px1);
            float iy1 = fmaxf(y1, py1);
            float ix2 = fminf(x2, px2);
            float iy2 = fminf(y2, py2);
            float inter = fmaxf(ix2 - ix1, 0.0f) * fmaxf(iy2 - iy1, 0.0f);
            float carea = (x2 - x1) * (y2 - y1);
            sm.sbelong[k] = inter / (carea + 1e-6f);
        }
    }
    __syncthreads();

    // ---- belong validity + fallback (lines / chars) ----
    if (level > 0) {
        if (tid == 0) {
            int any = 0;
            float best = -__int_as_float(0x7f800000);  // -inf
            int bi = 0;
            for (int k2 = 0; k2 < TOPK; ++k2) {
                if (sm.skeep[k2]) {
                    float bl = sm.sbelong[k2];
                    if (bl > best) { best = bl; bi = k2; }
                    if (bl > 0.6f) any = 1;
                }
            }
            sm.flag_any_vk = any;
            sm.argmax_idx  = bi;
        }
        __syncthreads();
        if (tid < TOPK) {
            bool valid = sm.sbelong[tid] > 0.6f;
            if (!sm.flag_any_vk) valid = (tid == sm.argmax_idx);
            if (!valid) sm.skeep[tid] = 0;
        }
        __syncthreads();
    }

    // ---- sequential NMS scan (thread j owns column j) ----
    for (int i = 0; i < TOPK - 1; ++i) {
        __syncthreads();
        if (tid > i && tid < TOPK && sm.skeep[i] && sm.skeep[tid]) {
            float ix1 = fmaxf(sm.sbox[i][0], sm.sbox[tid][0]);
            float iy1 = fmaxf(sm.sbox[i][1], sm.sbox[tid][1]);
            float ix2 = fminf(sm.sbox[i][2], sm.sbox[tid][2]);
            float iy2 = fminf(sm.sbox[i][3], sm.sbox[tid][3]);
            float inter = fmaxf(ix2 - ix1, 0.0f) * fmaxf(iy2 - iy1, 0.0f);
            float iou = inter / (sm.sarea[i] + sm.sarea[tid] - inter);
            if (iou > 0.1f) sm.skeep[tid] = 0;   // NaN > thr is false, matches JAX
        }
    }
    __syncthreads();

    // ---- write outputs ----
    size_t data_off, score_off, keep_off; int D;
    if (level == 0)      { D = 4;  data_off = 0;      score_off = 25600;  keep_off = 32000;  }
    else if (level == 1) { D = 4;  data_off = 38400;  score_off = 64000;  keep_off = 70400;  }
    else                 { D = 16; data_off = 76800;  score_off = 179200; keep_off = 185600; }

    float* dp = out + data_off + (size_t)b * TOPK * D;
    for (int idx = tid; idx < TOPK * D; idx += NTHREADS) {
        int k = idx / D;
        dp[idx] = sm.skeep[k] ? sm.sdat[k][idx - k * D] : 0.0f;
    }
    if (tid < TOPK) {
        out[score_off + (size_t)b * TOPK + tid] = sm.skeep[tid] ? sm.sval[tid] : 0.0f;
        out[keep_off  + (size_t)b * TOPK + tid] = sm.skeep[tid] ? 1.0f : 0.0f;
    }
}

extern "C" void kernel_launch(void* const* d_in, const int* in_sizes, int n_in,
                              void* d_out, int out_size) {
    (void)in_sizes; (void)n_in; (void)out_size;
    postprocess_kernel<<<dim3(B_IMGS, 3), NTHREADS>>>(
        (const float*)d_in[0],   // pred_block_logits
        (const float*)d_in[1],   // pred_line_logits
        (const float*)d_in[2],   // pred_char_logits
        (const float*)d_in[3],   // pred_block
        (const float*)d_in[4],   // pred_line
        (const float*)d_in[5],   // pred_char
        (const float*)d_in[6],   // target_sizes
        (float*)d_out);
}

// round 2
// speedup vs baseline: 1.5112x; 1.5112x over previous
#include <cuda_runtime.h>
#include <math.h>

#define B_IMGS   64
#define NBLK     4096
#define NLIN     16384
#define NCHR     16384
#define TOPK     100
#define KSEL     128      // top-128 by logit (supset), re-rank by exact sigmoid
#define NT       512
#define FASTCAP  512      // switch to 1-elem/thread fast path when survivors <= this

// Output layout (float32), reference return order (*blk, *lin, *chr):
//  blk_data [64,100,4]  @ 0
//  blk_scores [64,100]  @ 25600
//  blk_keep  [64,100]   @ 32000
//  lin_data [64,100,4]  @ 38400
//  lin_scores [64,100]  @ 64000
//  lin_keep  [64,100]   @ 70400
//  chr_data [64,100,16] @ 76800
//  chr_scores [64,100]  @ 179200
//  chr_keep  [64,100]   @ 185600   (total 192000)

struct SharedState {
    int totals[32];
    int cnt;           // gathered candidate count
    int cnt2;          // final (>= pivot) count
    int flag_any_vk;
    int argmax_idx;
    unsigned int ckey[FASTCAP];
    int          cidx[FASTCAP];
    float        fprob[FASTCAP];
    int          fidx[FASTCAP];
    float sval[TOPK];
    int   sidx[TOPK];
    float sbox[TOPK][4];
    float sarea[TOPK];
    float sbelong[TOPK];
    int   skeep[TOPK];
    float sdat[TOPK][16];
    unsigned int adj[TOPK][4];
    unsigned int keepw[4];
};

template<int LOC>
__device__ __forceinline__ void pp_body(
    SharedState& sm, int level, int b, int tid,
    const float* __restrict__ blk_logit,
    const float* __restrict__ lin_logit,
    const float* __restrict__ chr_logit,
    const float* __restrict__ blk_raw,
    const float* __restrict__ lin_raw,
    const float* __restrict__ chr_raw,
    const float* __restrict__ tsz,
    float* __restrict__ out)
{
    const int N = LOC * NT;   // 4096 or 16384, exact
    const float* logit = (level == 0) ? blk_logit : (level == 1) ? lin_logit : chr_logit;
    const float* lb = logit + (size_t)b * N;

    // ---- load logits -> monotone uint keys (registers) ----
    unsigned int lk[LOC];
#pragma unroll
    for (int r = 0; r < LOC; ++r) {
        unsigned int u = __float_as_uint(lb[tid + r * NT]);
        lk[r] = u ^ (((unsigned int)((int)u >> 31)) | 0x80000000u);
    }

    if (tid < 32) sm.totals[tid] = 0;
    if (tid == 0) { sm.cnt = 0; sm.cnt2 = 0; sm.flag_any_vk = 0; sm.argmax_idx = 0; }
    __syncthreads();

    // ---- phase 1: bitwise binary search on registers, exit when survivors small ----
    unsigned int prefix = 0u;
    int cnt_cur = N;
    int bit = 31;
    for (; bit >= 0; --bit) {
        if (cnt_cur <= FASTCAP) break;
        unsigned int cand = prefix | (1u << bit);
        int c = 0;
#pragma unroll
        for (int r = 0; r < LOC; ++r) c += (lk[r] >= cand) ? 1 : 0;
#pragma unroll
        for (int off = 16; off > 0; off >>= 1) c += __shfl_down_sync(0xFFFFFFFFu, c, off);
        if ((tid & 31) == 0 && c) atomicAdd(&sm.totals[bit], c);
        __syncthreads();
        int tot = sm.totals[bit];
        if (tot >= KSEL) { prefix = cand; cnt_cur = tot; }
    }

    // ---- phase 2: gather survivors (key >= prefix) to shared ----
#pragma unroll
    for (int r = 0; r < LOC; ++r) {
        if (lk[r] >= prefix) {
            int p = atomicAdd(&sm.cnt, 1);
            if (p < FASTCAP) { sm.ckey[p] = lk[r]; sm.cidx[p] = tid + r * NT; }
        }
    }
    __syncthreads();
    const int cg = min(sm.cnt, FASTCAP);
    const unsigned int mykey = (tid < cg) ? sm.ckey[tid] : 0u;
    const int myidx = (tid < cg) ? sm.cidx[tid] : 0;

    // ---- phase 3: finish binary search, 1 elem/thread via syncthreads_count ----
    for (; bit >= 0; --bit) {
        unsigned int cand = prefix | (1u << bit);
        int c = __syncthreads_count((tid < cg) && (mykey >= cand));
        if (c >= KSEL) prefix = cand;
    }
    // prefix = exact KSEL-th largest key (pivot)

    // ---- phase 4: compact (key >= pivot), exact f32 sigmoid per candidate ----
    if (tid < cg && mykey >= prefix) {
        int p = atomicAdd(&sm.cnt2, 1);
        unsigned int u = mykey ^ ((mykey & 0x80000000u) ? 0x80000000u : 0xFFFFFFFFu);
        float x = __uint_as_float(u);
        double e = exp(-(double)x);
        sm.fprob[p] = (float)(1.0 / (1.0 + e));
        sm.fidx[p]  = myidx;
    }
    __syncthreads();
    const int M = sm.cnt2;   // >= 128 for this data

    // ---- rank by (prob desc, index asc) — lax.top_k semantics ----
    if (tid < M) {
        float pm = sm.fprob[tid];
        int   im = sm.fidx[tid];
        int rank = 0;
        for (int j = 0; j < M; ++j) {
            float pj = sm.fprob[j];
            int   ij = sm.fidx[j];
            rank += (pj > pm || (pj == pm && ij < im)) ? 1 : 0;
        }
        if (rank < TOPK) { sm.sval[rank] = pm; sm.sidx[rank] = im; }
    }
    __syncthreads();

    const float hh = tsz[2 * b + 0];   // img_h
    const float ww = tsz[2 * b + 1];   // img_w

    // ---- per-detection geometry ----
    if (tid < TOPK) {
        const int k  = tid;
        const int si = sm.sidx[k];
        float x1, y1, x2, y2;

        if (level == 2) {
            const float* rp = chr_raw + ((size_t)b * NCHR + (size_t)si) * 16;
            float ctrl[16];
#pragma unroll
            for (int j = 0; j < 8; ++j) {
                ctrl[2 * j]     = rp[2 * j]     * hh;
                ctrl[2 * j + 1] = rp[2 * j + 1] * ww;
            }
            float mnx = 1e30f, mny = 1e30f, mxx = -1e30f, mxy = -1e30f;
#pragma unroll
            for (int s = 0; s < 10; ++s) {
                float t  = (float)s * (1.0f / 9.0f);
                float ti = 1.0f - t;
                float b0 = ti * ti * ti;
                float b1 = 3.0f * t * ti * ti;
                float b2 = 3.0f * t * t * ti;
                float b3 = t * t * t;
                float xt = b0 * ctrl[0] + b1 * ctrl[2]  + b2 * ctrl[4]  + b3 * ctrl[6];
                float yt = b0 * ctrl[1] + b1 * ctrl[3]  + b2 * ctrl[5]  + b3 * ctrl[7];
                float xb = b0 * ctrl[8] + b1 * ctrl[10] + b2 * ctrl[12] + b3 * ctrl[14];
                float yb = b0 * ctrl[9] + b1 * ctrl[11] + b2 * ctrl[13] + b3 * ctrl[15];
                mnx = fminf(mnx, fminf(xt, xb));
                mny = fminf(mny, fminf(yt, yb));
                mxx = fmaxf(mxx, fmaxf(xt, xb));
                mxy = fmaxf(mxy, fmaxf(yt, yb));
            }
            x1 = mnx; y1 = mny; x2 = mxx; y2 = mxy;
#pragma unroll
            for (int j = 0; j < 16; ++j) sm.sdat[k][j] = ctrl[j];
        } else {
            const float* rp = (level == 0)
                ? blk_raw + ((size_t)b * NBLK + (size_t)si) * 4
                : lin_raw + ((size_t)b * NLIN + (size_t)si) * 4;
            float cx = rp[0], cy = rp[1], bw = rp[2], bh = rp[3];
            x1 = (cx - 0.5f * bw) * ww;
            y1 = (cy - 0.5f * bh) * hh;
            x2 = (cx + 0.5f * bw) * ww;
            y2 = (cy + 0.5f * bh) * hh;
            if (level == 0) {
                x1 = fminf(fmaxf(x1, 0.0f), ww);
                y1 = fminf(fmaxf(y1, 0.0f), hh);
                x2 = fminf(fmaxf(x2, 0.0f), ww);
                y2 = fminf(fmaxf(y2, 0.0f), hh);
            }
            sm.sdat[k][0] = x1; sm.sdat[k][1] = y1;
            sm.sdat[k][2] = x2; sm.sdat[k][3] = y2;
        }

        sm.sbox[k][0] = x1; sm.sbox[k][1] = y1;
        sm.sbox[k][2] = x2; sm.sbox[k][3] = y2;
        sm.sarea[k] = (x2 - x1) * (y2 - y1);

        bool kp   = sm.sval[k] > 0.1f;
        bool anyk = sm.sval[0] > 0.1f;
        if (!anyk) kp = (k == 0);
        sm.skeep[k] = kp ? 1 : 0;

        if (level > 0) {
            const float* pr = (level == 1)
                ? blk_raw + ((size_t)b * NBLK + (size_t)(si >> 2)) * 4   // ef=4
                : lin_raw + ((size_t)b * NLIN + (size_t)si) * 4;         // ef=1
            float pcx = pr[0], pcy = pr[1], pw = pr[2], ph = pr[3];
            float px1 = (pcx - 0.5f * pw) * ww;
            float py1 = (pcy - 0.5f * ph) * hh;
            float px2 = (pcx + 0.5f * pw) * ww;
            float py2 = (pcy + 0.5f * ph) * hh;
            float ix1 = fmaxf(x1, px1);
            float iy1 = fmaxf(y1, py1);
            float ix2 = fminf(x2, px2);
            float iy2 = fminf(y2, py2);
            float inter = fmaxf(ix2 - ix1, 0.0f) * fmaxf(iy2 - iy1, 0.0f);
            float carea = (x2 - x1) * (y2 - y1);
            sm.sbelong[k] = inter / (carea + 1e-6f);
        }
    }
    __syncthreads();

    // ---- belong validity + fallback (lines / chars) ----
    if (level > 0) {
        if (tid == 0) {
            int any = 0;
            float best = -__int_as_float(0x7f800000);  // -inf
            int bi = 0;
            for (int k2 = 0; k2 < TOPK; ++k2) {
                if (sm.skeep[k2]) {
                    float bl = sm.sbelong[k2];
                    if (bl > best) { best = bl; bi = k2; }
                    if (bl > 0.6f) any = 1;
                }
            }
            sm.flag_any_vk = any;
            sm.argmax_idx  = bi;
        }
        __syncthreads();
        if (tid < TOPK) {
            bool valid = sm.sbelong[tid] > 0.6f;
            if (!sm.flag_any_vk) valid = (tid == sm.argmax_idx);
            if (!valid) sm.skeep[tid] = 0;
        }
        __syncthreads();
    }

    // ---- NMS: build adjacency bitmask in parallel ----
    {
        const int warp = tid >> 5, lane = tid & 31;
        for (int task = warp; task < TOPK * 4; task += NT / 32) {
            const int i = task >> 2, w = task & 3;
            const int j = w * 32 + lane;
            bool pred = false;
            if (j < TOPK && j > i) {
                float ix1 = fmaxf(sm.sbox[i][0], sm.sbox[j][0]);
                float iy1 = fmaxf(sm.sbox[i][1], sm.sbox[j][1]);
                float ix2 = fminf(sm.sbox[i][2], sm.sbox[j][2]);
                float iy2 = fminf(sm.sbox[i][3], sm.sbox[j][3]);
                float inter = fmaxf(ix2 - ix1, 0.0f) * fmaxf(iy2 - iy1, 0.0f);
                float iou = inter / (sm.sarea[i] + sm.sarea[j] - inter);
                pred = iou > 0.1f;    // NaN-safe: false, matches JAX
            }
            unsigned int m = __ballot_sync(0xFFFFFFFFu, pred);
            if (lane == 0) sm.adj[i][w] = m;
        }
        if (tid < 128) {
            bool kp = (tid < TOPK) && (sm.skeep[tid] != 0);
            unsigned int m = __ballot_sync(0xFFFFFFFFu, kp);
            if ((tid & 31) == 0) sm.keepw[tid >> 5] = m;
        }
    }
    __syncthreads();

    // ---- sequential suppression scan: single thread, branchless word ops ----
    if (tid == 0) {
        unsigned int k0 = sm.keepw[0], k1 = sm.keepw[1], k2 = sm.keepw[2], k3 = sm.keepw[3];
#pragma unroll
        for (int i = 0; i < TOPK; ++i) {
            unsigned int ki = (i < 32) ? k0 : (i < 64) ? k1 : (i < 96) ? k2 : k3;
            unsigned int bm = (unsigned int)(-(int)((ki >> (i & 31)) & 1u));
            k0 &= ~(sm.adj[i][0] & bm);
            k1 &= ~(sm.adj[i][1] & bm);
            k2 &= ~(sm.adj[i][2] & bm);
            k3 &= ~(sm.adj[i][3] & bm);
        }
        sm.keepw[0] = k0; sm.keepw[1] = k1; sm.keepw[2] = k2; sm.keepw[3] = k3;
    }
    __syncthreads();
    if (tid < TOPK) sm.skeep[tid] = (sm.keepw[tid >> 5] >> (tid & 31)) & 1u;
    __syncthreads();

    // ---- write outputs ----
    size_t data_off, score_off, keep_off; int D;
    if (level == 0)      { D = 4;  data_off = 0;      score_off = 25600;  keep_off = 32000;  }
    else if (level == 1) { D = 4;  data_off = 38400;  score_off = 64000;  keep_off = 70400;  }
    else                 { D = 16; data_off = 76800;  score_off = 179200; keep_off = 185600; }

    float* dp = out + data_off + (size_t)b * TOPK * D;
    for (int idx = tid; idx < TOPK * D; idx += NT) {
        int k = idx / D;
        dp[idx] = sm.skeep[k] ? sm.sdat[k][idx - k * D] : 0.0f;
    }
    if (tid < TOPK) {
        out[score_off + (size_t)b * TOPK + tid] = sm.skeep[tid] ? sm.sval[tid] : 0.0f;
        out[keep_off  + (size_t)b * TOPK + tid] = sm.skeep[tid] ? 1.0f : 0.0f;
    }
}

__global__ void __launch_bounds__(NT)
postprocess_kernel(const float* __restrict__ blk_logit,
                   const float* __restrict__ lin_logit,
                   const float* __restrict__ chr_logit,
                   const float* __restrict__ blk_raw,
                   const float* __restrict__ lin_raw,
                   const float* __restrict__ chr_raw,
                   const float* __restrict__ tsz,
                   float* __restrict__ out)
{
    __shared__ SharedState sm;
    const int b     = blockIdx.x;
    const int level = blockIdx.y;
    const int tid   = threadIdx.x;
    if (level == 0) {
        pp_body<8>(sm, 0, b, tid, blk_logit, lin_logit, chr_logit,
                   blk_raw, lin_raw, chr_raw, tsz, out);
    } else {
        pp_body<32>(sm, level, b, tid, blk_logit, lin_logit, chr_logit,
                    blk_raw, lin_raw, chr_raw, tsz, out);
    }
}

extern "C" void kernel_launch(void* const* d_in, const int* in_sizes, int n_in,
                              void* d_out, int out_size) {
    (void)in_sizes; (void)n_in; (void)out_size;
    postprocess_kernel<<<dim3(B_IMGS, 3), NT>>>(
        (const float*)d_in[0],   // pred_block_logits
        (const float*)d_in[1],   // pred_line_logits
        (const float*)d_in[2],   // pred_char_logits
        (const float*)d_in[3],   // pred_block
        (const float*)d_in[4],   // pred_line
        (const float*)d_in[5],   // pred_char
        (const float*)d_in[6],   // target_sizes
        (float*)d_out);
}